// round 2
// baseline (speedup 1.0000x reference)
#include <cuda_runtime.h>

// Problem: out[b,0,v] = sum_c x[b,c,v]*conv_w[c] + conv_b
//                     + (w[b]*scale[b]) * sum_c x[b,c,v] + shift[b]
// Fused:   out[b,v]   = sum_c x[b,c,v] * coef[b][c] + bias[b]
// with coef[b][c] = conv_w[c] + w[b]*scale[b], bias[b] = conv_b + shift[b],
// where s = silu(z_prjs[b]), w = s.hwd_w + hwd_b, scale = s.c_w[0] + c_b[0],
// shift = s.c_w[1] + c_b[1].

#define BATCH 8
#define CH    16
#define SPATIAL (96*96*96)          // 884736 floats per (b,c) plane
#define N4    (SPATIAL/4)           // 221184 float4 per plane
#define TPB   256
#define BLOCKS_PER_B (N4 / TPB)     // 864, exact

__device__ float g_coef[BATCH][CH];
__device__ float g_bias[BATCH];

__device__ __forceinline__ float silu_f(float v) {
    return v / (1.0f + __expf(-v));
}

__global__ void precompute_kernel(const float* __restrict__ z_prjs,   // [B,5]
                                  const float* __restrict__ conv_w,   // [1,16]
                                  const float* __restrict__ conv_b,   // [1]
                                  const float* __restrict__ hwd_w,    // [1,5]
                                  const float* __restrict__ hwd_b,    // [1]
                                  const float* __restrict__ c_w,      // [2,5]
                                  const float* __restrict__ c_b)      // [2]
{
    int b = threadIdx.x;
    if (b >= BATCH) return;

    float s[5];
    #pragma unroll
    for (int j = 0; j < 5; j++) s[j] = silu_f(z_prjs[b * 5 + j]);

    float w = hwd_b[0], scale = c_b[0], shift = c_b[1];
    #pragma unroll
    for (int j = 0; j < 5; j++) {
        w     += s[j] * hwd_w[j];
        scale += s[j] * c_w[j];        // c_w row 0
        shift += s[j] * c_w[5 + j];    // c_w row 1
    }

    float ws = w * scale;
    g_bias[b] = conv_b[0] + shift;
    #pragma unroll
    for (int c = 0; c < CH; c++) g_coef[b][c] = conv_w[c] + ws;
}

__global__ __launch_bounds__(TPB) void fused_reduce_kernel(
    const float* __restrict__ x,   // [B, C, SPATIAL]
    float* __restrict__ out)       // [B, 1, SPATIAL]
{
    const int b = blockIdx.y;

    __shared__ float sc[CH + 1];
    if (threadIdx.x < CH)        sc[threadIdx.x] = g_coef[b][threadIdx.x];
    else if (threadIdx.x == CH)  sc[CH] = g_bias[b];
    __syncthreads();

    const int idx = blockIdx.x * TPB + threadIdx.x;       // float4 index in plane
    const float4* __restrict__ x4 =
        reinterpret_cast<const float4*>(x) + (size_t)b * CH * N4 + idx;

    // Front-batched loads: 16 independent LDG.128 in flight per thread (MLP=16).
    float4 v[CH];
    #pragma unroll
    for (int c = 0; c < CH; c++) v[c] = x4[(size_t)c * N4];

    float bias = sc[CH];
    float4 acc = make_float4(bias, bias, bias, bias);
    #pragma unroll
    for (int c = 0; c < CH; c++) {
        float k = sc[c];
        acc.x += v[c].x * k;
        acc.y += v[c].y * k;
        acc.z += v[c].z * k;
        acc.w += v[c].w * k;
    }

    reinterpret_cast<float4*>(out)[(size_t)b * N4 + idx] = acc;
}

extern "C" void kernel_launch(void* const* d_in, const int* in_sizes, int n_in,
                              void* d_out, int out_size)
{
    const float* x      = (const float*)d_in[0];
    const float* z_prjs = (const float*)d_in[1];
    const float* conv_w = (const float*)d_in[2];
    const float* conv_b = (const float*)d_in[3];
    const float* hwd_w  = (const float*)d_in[4];
    const float* hwd_b  = (const float*)d_in[5];
    const float* c_w    = (const float*)d_in[6];
    const float* c_b    = (const float*)d_in[7];
    float* out = (float*)d_out;

    precompute_kernel<<<1, 32>>>(z_prjs, conv_w, conv_b, hwd_w, hwd_b, c_w, c_b);

    dim3 grid(BLOCKS_PER_B, BATCH);
    fused_reduce_kernel<<<grid, TPB>>>(x, out);
}

// round 4
// speedup vs baseline: 1.0106x; 1.0106x over previous
#include <cuda_runtime.h>

// Fused: out[b,v] = sum_c x[b,c,v] * coef[b][c] + bias[b]
//   coef[b][c] = conv_w[c] + w[b]*scale[b], bias[b] = conv_b + shift[b]
//   s = silu(z_prjs[b]); w = s.hwd_w + hwd_b; scale = s.c_w[0]+c_b[0]; shift = s.c_w[1]+c_b[1]
// Single kernel: first 17 threads of each CTA recompute the (tiny) coefficients;
// params are 8 cache lines, L2-resident after the first wave.

#define BATCH 8
#define CH    16
#define SPATIAL (96*96*96)          // 884736 floats per (b,c) plane
#define N4    (SPATIAL/4)           // 221184 float4 per plane
#define TPB   256
#define BLOCKS_PER_B (N4 / TPB)     // 864, exact

__device__ __forceinline__ float silu_f(float v) {
    return v / (1.0f + __expf(-v));
}

__global__ __launch_bounds__(TPB) void fused_kernel(
    const float* __restrict__ x,        // [B, C, SPATIAL]
    const float* __restrict__ z_prjs,   // [B,5]
    const float* __restrict__ conv_w,   // [1,16]
    const float* __restrict__ conv_b,   // [1]
    const float* __restrict__ hwd_w,    // [1,5]
    const float* __restrict__ hwd_b,    // [1]
    const float* __restrict__ c_w,      // [2,5]
    const float* __restrict__ c_b,      // [2]
    float* __restrict__ out)            // [B, 1, SPATIAL]
{
    const int b = blockIdx.y;

    __shared__ float sc[CH + 1];

    // Threads 0..16 redundantly compute the per-batch scalars (tiny; L2-hit).
    if (threadIdx.x <= CH) {
        float s0 = silu_f(z_prjs[b * 5 + 0]);
        float s1 = silu_f(z_prjs[b * 5 + 1]);
        float s2 = silu_f(z_prjs[b * 5 + 2]);
        float s3 = silu_f(z_prjs[b * 5 + 3]);
        float s4 = silu_f(z_prjs[b * 5 + 4]);

        if (threadIdx.x < CH) {
            float w  = hwd_b[0] + s0*hwd_w[0] + s1*hwd_w[1] + s2*hwd_w[2]
                                 + s3*hwd_w[3] + s4*hwd_w[4];
            float sl = c_b[0]   + s0*c_w[0]   + s1*c_w[1]   + s2*c_w[2]
                                 + s3*c_w[3]   + s4*c_w[4];
            sc[threadIdx.x] = conv_w[threadIdx.x] + w * sl;
        } else {
            float sh = c_b[1]   + s0*c_w[5]   + s1*c_w[6]   + s2*c_w[7]
                                 + s3*c_w[8]   + s4*c_w[9];
            sc[CH] = conv_b[0] + sh;
        }
    }
    __syncthreads();

    const int idx = blockIdx.x * TPB + threadIdx.x;       // float4 index in plane
    const float4* __restrict__ x4 =
        reinterpret_cast<const float4*>(x) + (size_t)b * CH * N4 + idx;

    // Front-batched loads: 16 independent LDG.128 in flight per thread (MLP=16).
    float4 v[CH];
    #pragma unroll
    for (int c = 0; c < CH; c++) v[c] = x4[(size_t)c * N4];

    float bias = sc[CH];
    float4 acc = make_float4(bias, bias, bias, bias);
    #pragma unroll
    for (int c = 0; c < CH; c++) {
        float k = sc[c];
        acc.x += v[c].x * k;
        acc.y += v[c].y * k;
        acc.z += v[c].z * k;
        acc.w += v[c].w * k;
    }

    reinterpret_cast<float4*>(out)[(size_t)b * N4 + idx] = acc;
}

extern "C" void kernel_launch(void* const* d_in, const int* in_sizes, int n_in,
                              void* d_out, int out_size)
{
    const float* x      = (const float*)d_in[0];
    const float* z_prjs = (const float*)d_in[1];
    const float* conv_w = (const float*)d_in[2];
    const float* conv_b = (const float*)d_in[3];
    const float* hwd_w  = (const float*)d_in[4];
    const float* hwd_b  = (const float*)d_in[5];
    const float* c_w    = (const float*)d_in[6];
    const float* c_b    = (const float*)d_in[7];
    float* out = (float*)d_out;

    dim3 grid(BLOCKS_PER_B, BATCH);
    fused_kernel<<<grid, TPB>>>(x, z_prjs, conv_w, conv_b, hwd_w, hwd_b,
                                c_w, c_b, out);
}